// round 11
// baseline (speedup 1.0000x reference)
#include <cuda_runtime.h>

// SAXS P(r) L1 loss — Round 7.
// vs R6: back to 1-RMW/pair dual-field u32 private histograms, but only for
// the hot range (words 0..102, d<=51.2A ~ 99.6% of pairs) so 256-thread
// blocks keep 2 blocks/SM (16 warps). Rare far pairs (~0.4%) go to a tiny
// per-block parity-packed u64 smem-atomic histogram (idle ATOMS backend).
// Distance math vectorized with sm_103a f32x2 (add/fma.rn.f32x2): 6 packed
// ops replace 12 scalar FP per 2 pairs. Magic-number rounding retained;
// clamp applied on d2 (keeps magic-add safe for displaced masked atoms).
// MLP=2 RMW batching with equal-offset merge (lost-update safe).

namespace {
constexpr int   kNBins      = 201;
constexpr int   kNAtoms     = 9472;                       // 256*37
constexpr int   kTile       = 128;
constexpr int   kNTiles     = kNAtoms / kTile;            // 74
constexpr int   kNPairTiles = kNTiles * (kNTiles + 1) / 2;   // 2775
constexpr int   kBlocksX    = 148;
constexpr int   kThreads    = 256;
constexpr float kPre        = 512.0f;                     // 256 / STEP
constexpr float kD2Max      = 2.70045e9f;                 // (~51966)^2 -> word 202 discard
constexpr int   kWords      = 104;                        // 0..102 live, 103 trash
constexpr int   kHistU32    = kWords * kThreads;          // 26624
constexpr int   kParU32     = 2 * 208;                    // pA[208], pB[208]
constexpr int   kSmemBytes  = (kHistU32 + kParU32) * 4 + 256 * 16;  // 112256
constexpr unsigned kTrashOff = 103u * 1024u;
}

__device__ float4       g_pos[2][kNAtoms];
__device__ unsigned int g_hist[2][256];
__device__ unsigned int g_done;

#define ADD2(out, a, b) \
    asm("add.rn.f32x2 %0, %1, %2;" : "=l"(out) : "l"(a), "l"(b))
#define MUL2(out, a, b) \
    asm("mul.rn.f32x2 %0, %1, %2;" : "=l"(out) : "l"(a), "l"(b))
#define FMA2(out, a, b, c) \
    asm("fma.rn.f32x2 %0, %1, %2, %3;" : "=l"(out) : "l"(a), "l"(b), "l"(c))
#define PACK2(out, lo, hi) \
    asm("mov.b64 %0, {%1, %2};" : "=l"(out) : "f"(lo), "f"(hi))
#define UNPACK2(lo, hi, in) \
    asm("mov.b64 {%0, %1}, %2;" : "=f"(lo), "=f"(hi) : "l"(in))

// ---------------------------------------------------------------------------
__global__ void prepack_kernel(const float* __restrict__ pred,
                               const float* __restrict__ tru,
                               const float* __restrict__ mask) {
    int i = blockIdx.x * blockDim.x + threadIdx.x;
    if (i == 0) g_done = 0u;
    if (i < 512) ((unsigned int*)g_hist)[i] = 0u;
    if (i >= kNAtoms) return;
    float m = mask[i];
    if (m != 0.0f) {
        g_pos[0][i] = make_float4(pred[3*i+0]*kPre, pred[3*i+1]*kPre, pred[3*i+2]*kPre, 0.f);
        g_pos[1][i] = make_float4(tru [3*i+0]*kPre, tru [3*i+1]*kPre, tru [3*i+2]*kPre, 0.f);
    } else {
        float dx = 1.0e8f + (float)i * 2.0e5f;   // displaced -> d2 clamp -> discard
        g_pos[0][i] = make_float4(dx, 0.f, 0.f, 0.f);
        g_pos[1][i] = make_float4(dx, 0.f, 0.f, 0.f);
    }
}

// ---------------------------------------------------------------------------
__device__ __forceinline__ void decode_tile(int p, int& bi, int& bj) {
    double Td = (double)kNTiles;
    int b = (int)(((2.0 * Td + 1.0) -
                   sqrt((2.0 * Td + 1.0) * (2.0 * Td + 1.0) - 8.0 * (double)p)) * 0.5);
    if (b < 0) b = 0;
    if (b > kNTiles - 1) b = kNTiles - 1;
    while (b * (2 * kNTiles - b + 1) / 2 > p) --b;
    while ((b + 1) * (2 * kNTiles - b) / 2 <= p) ++b;
    bi = b;
    bj = b + (p - b * (2 * kNTiles - b + 1) / 2);
}

// Rare (w >= 103) path: parity-packed u64 smem atomic.
__device__ __forceinline__ void rare_add(unsigned* pA, unsigned* pB,
                                         unsigned w, unsigned q) {
    unsigned long long v = ((unsigned long long)q << 32)
                         | (unsigned long long)(256u - q);
    unsigned* addr = (w & 1u) ? (pB + w + 1) : (pA + w);
    atomicAdd((unsigned long long*)addr, v);
}

// Two pairs: packed f32x2 distance chain, magic rounding, 1 RMW/pair.
__device__ __forceinline__ void process2(char* hb, unsigned* pA, unsigned* pB,
    unsigned long long rx2, unsigned long long ry2, unsigned long long rz2,
    unsigned long long ax2, unsigned long long ay2, unsigned long long az2,
    bool k0, bool k1)
{
    unsigned long long dx2, dy2, dz2, zz, yy, dd;
    ADD2(dx2, rx2, ax2);                  // rj + (-ai)
    ADD2(dy2, ry2, ay2);
    ADD2(dz2, rz2, az2);
    MUL2(zz, dz2, dz2);
    FMA2(yy, dy2, dy2, zz);
    FMA2(dd, dx2, dx2, yy);
    float d2l, d2h;
    UNPACK2(d2l, d2h, dd);
    d2l = fminf(d2l, kD2Max);             // keeps magic-add in range; far -> word 202
    d2h = fminf(d2h, kD2Max);
    float r0 = rsqrtf(d2l);
    float r1 = rsqrtf(d2h);
    float t0 = d2l * r0;                  // = d * 256/STEP
    float t1 = d2h * r1;
    unsigned i0 = __float_as_uint(t0 + 12582912.0f);   // rn(t) in mantissa
    unsigned i1 = __float_as_uint(t1 + 12582912.0f);
    unsigned q0 = i0 & 255u,  q1 = i1 & 255u;
    unsigned off0 = (i0 << 2) & 0x7FC00u;              // word(b>>8) * 1024
    unsigned off1 = (i1 << 2) & 0x7FC00u;
    unsigned val0 = q0 * 65535u + 256u;                // (256-q) | (q<<16)
    unsigned val1 = q1 * 65535u + 256u;
    bool rare0 = off0 > 102u * 1024u;
    bool rare1 = off1 > 102u * 1024u;
    if (k0) { off0 = kTrashOff; rare0 = false; }
    if (k1) { off1 = kTrashOff; rare1 = false; }
    if (!(rare0 || rare1)) {
        if (off0 == off1) { val0 += val1; off1 = kTrashOff; }  // merge: no lost update
        unsigned a0 = *(unsigned*)(hb + off0);
        unsigned a1 = *(unsigned*)(hb + off1);
        *(unsigned*)(hb + off0) = a0 + val0;
        *(unsigned*)(hb + off1) = a1 + val1;
    } else {
        if (rare0) rare_add(pA, pB, off0 >> 10, q0);
        else       *(unsigned*)(hb + off0) += val0;
        if (rare1) rare_add(pA, pB, off1 >> 10, q1);
        else       *(unsigned*)(hb + off1) += val1;
    }
}

// ---------------------------------------------------------------------------
__global__ __launch_bounds__(kThreads, 2)
void pair_hist_kernel(float* __restrict__ out) {
    extern __shared__ unsigned int smem[];
    unsigned int* hist = smem;                         // [104][256]
    unsigned int* pA   = smem + kHistU32;              // [208]
    unsigned int* pB   = pA + 208;                     // [208]
    float4* buf = (float4*)(smem + kHistU32 + kParU32);  // [256]

    const int s   = blockIdx.y;
    const int tid = threadIdx.x;
    const int tx  = tid & 15;     // cols tx*8 + v
    const int ty  = tid >> 4;     // rows ty*8 + u
    char* hb = (char*)hist + tid * 4;                  // bank = tid&31

#pragma unroll 4
    for (int w = 0; w < kWords; ++w) hist[(w << 8) + tid] = 0u;
    if (tid < 208) { pA[tid] = 0u; pB[tid] = 0u; }

    int p = blockIdx.x;
    int bi, bj;
    decode_tile(p, bi, bj);
    {
        int idx = (tid < 128) ? (bi * kTile + tid) : (bj * kTile + tid - 128);
        buf[tid] = g_pos[s][idx];
    }
    __syncthreads();

    for (;;) {
        const int pn = p + kBlocksX;
        const bool havenext = (pn < kNPairTiles);
        float4 nxt; int bin_ = 0, bjn = 0;
        if (havenext) {                               // prefetch into registers
            decode_tile(pn, bin_, bjn);
            int idx = (tid < 128) ? (bin_ * kTile + tid) : (bjn * kTile + tid - 128);
            nxt = g_pos[s][idx];
        }

        const float4* ti = buf;
        const float4* tj = buf + 128;

        // Pack this thread's 8 j-atoms as f32x2 pairs (raw; ai negated below).
        unsigned long long rx2[4], ry2[4], rz2[4];
#pragma unroll
        for (int v2 = 0; v2 < 4; ++v2) {
            float4 c0 = tj[tx * 8 + 2 * v2];
            float4 c1 = tj[tx * 8 + 2 * v2 + 1];
            PACK2(rx2[v2], c0.x, c1.x);
            PACK2(ry2[v2], c0.y, c1.y);
            PACK2(rz2[v2], c0.z, c1.z);
        }

        if (bi != bj) {
#pragma unroll 2
            for (int u = 0; u < 8; ++u) {
                float4 a4 = ti[ty * 8 + u];
                float nx = -a4.x, ny = -a4.y, nz = -a4.z;
                unsigned long long ax2, ay2, az2;
                PACK2(ax2, nx, nx); PACK2(ay2, ny, ny); PACK2(az2, nz, nz);
#pragma unroll
                for (int v2 = 0; v2 < 4; ++v2)
                    process2(hb, pA, pB, rx2[v2], ry2[v2], rz2[v2],
                             ax2, ay2, az2, false, false);
            }
        } else {
#pragma unroll 2
            for (int u = 0; u < 8; ++u) {
                const int iu = ty * 8 + u;
                float4 a4 = ti[iu];
                float nx = -a4.x, ny = -a4.y, nz = -a4.z;
                unsigned long long ax2, ay2, az2;
                PACK2(ax2, nx, nx); PACK2(ay2, ny, ny); PACK2(az2, nz, nz);
#pragma unroll
                for (int v2 = 0; v2 < 4; ++v2) {
                    const int jv = tx * 8 + 2 * v2;
                    process2(hb, pA, pB, rx2[v2], ry2[v2], rz2[v2],
                             ax2, ay2, az2, iu >= jv, iu >= jv + 1);
                }
            }
        }

        __syncthreads();
        if (!havenext) break;
        buf[tid] = nxt;
        __syncthreads();
        p = pn; bi = bin_; bj = bjn;
    }

    // ---- flush ----
    // Private dual-field: bin b (0..102) = low(word b) + high(word b-1).
    unsigned int* scratch = (unsigned int*)buf;        // tiles dead now
    unsigned slo = 0, shi = 0;
    if (tid < 103) {
        for (int i = 0; i < kThreads; ++i) {
            int t = (tid + i) & 255;                   // staggered, conflict-free
            unsigned v = hist[(tid << 8) + t];
            slo += v & 0xFFFFu;
            shi += v >> 16;
        }
        scratch[tid] = shi;
    }
    __syncthreads();
    if (tid < 103) {
        unsigned total = slo + (tid ? scratch[tid - 1] : 0u);
        if (total) atomicAdd(&g_hist[s][tid], total);
    } else if (tid == 103) {
        unsigned carry = scratch[102];                 // bin 103 from word 102 high
        if (carry) atomicAdd(&g_hist[s][103], carry);
    } else if (tid >= 104 && tid <= 202) {
        // Parity hist: bin w (103..201) = pA[w] + pB[w+1]; bin 201 folds to 200.
        int w = tid - 1;
        unsigned tot = pA[w] + pB[w + 1];
        if (tot) atomicAdd(&g_hist[s][w <= 200 ? w : 200], tot);
    }

    // ---- last block finalizes ----
    __threadfence();
    __shared__ unsigned int ticket;
    __syncthreads();
    if (tid == 0) ticket = atomicAdd(&g_done, 1u);
    __syncthreads();
    if (ticket != 2u * kBlocksX - 1u) return;
    __threadfence();

    double* sh = (double*)smem;
    volatile unsigned int* gh = (volatile unsigned int*)g_hist;
    double h0 = (tid < kNBins) ? (double)gh[tid]       : 0.0;
    double h1 = (tid < kNBins) ? (double)gh[256 + tid] : 0.0;

    sh[tid] = h0; __syncthreads();
    for (int o = 128; o > 0; o >>= 1) { if (tid < o) sh[tid] += sh[tid + o]; __syncthreads(); }
    double s0 = sh[0]; __syncthreads();

    sh[tid] = h1; __syncthreads();
    for (int o = 128; o > 0; o >>= 1) { if (tid < o) sh[tid] += sh[tid + o]; __syncthreads(); }
    double s1 = sh[0]; __syncthreads();

    sh[tid] = fabs(h0 / (s0 + 1e-12) - h1 / (s1 + 1e-12)); __syncthreads();
    for (int o = 128; o > 0; o >>= 1) { if (tid < o) sh[tid] += sh[tid + o]; __syncthreads(); }

    if (tid == 0) out[0] = (float)sh[0];
}

// ---------------------------------------------------------------------------
extern "C" void kernel_launch(void* const* d_in, const int* in_sizes, int n_in,
                              void* d_out, int out_size) {
    (void)in_sizes; (void)n_in; (void)out_size;
    const float* pred = (const float*)d_in[0];
    const float* tru  = (const float*)d_in[1];
    const float* mask = (const float*)d_in[2];

    cudaFuncSetAttribute(pair_hist_kernel,
                         cudaFuncAttributeMaxDynamicSharedMemorySize, kSmemBytes);

    prepack_kernel<<<(kNAtoms + 255) / 256, 256>>>(pred, tru, mask);

    dim3 grid(kBlocksX, 2);
    pair_hist_kernel<<<grid, kThreads, kSmemBytes>>>((float*)d_out);
}

// round 13
// speedup vs baseline: 1.2906x; 1.2906x over previous
#include <cuda_runtime.h>

// SAXS P(r) L1 loss — Round 9 (R8 with the diag-kill/rare-path bug fixed).
// R5 scalar inner loop (dual-field u32 private smem histograms, 1 RMW/pair,
// magic rounding, MLP=2 + equal-offset merge); private histogram covers
// words 0..133 (d<=67A, P(miss)~5e-5); rare far pairs -> parity-packed u64
// smem-atomic fallback. FIX vs R8: killed (diagonal) pairs are excluded from
// the rare path (rare flag computed pre-kill, forced false on kill) so they
// land only in the dead private word 135. Block smem 75.4KB -> 3 blocks/SM.

namespace {
constexpr int   kNBins      = 201;
constexpr int   kNAtoms     = 9472;                       // 256*37
constexpr int   kTile       = 128;
constexpr int   kNTiles     = kNAtoms / kTile;            // 74
constexpr int   kNPairTiles = kNTiles * (kNTiles + 1) / 2;   // 2775
constexpr int   kBlocksX    = 444;                        // 3 blocks/SM * 148 SM
constexpr int   kThreads    = 128;
constexpr float kPre        = 512.0f;                     // 256 / STEP
constexpr float kClampT     = 52223.0f;                   // word 203 (dropped)
constexpr int   kWords      = 136;   // 0..133 live, 134 merge-dead, 135 diag-dead
constexpr int   kHistU32    = kWords * kThreads;          // 17408 (69632 B)
constexpr int   kParU32     = 2 * 208;                    // pA[208], pB[208]
constexpr int   kSmemBytes  = (kHistU32 + kParU32) * 4 + 256 * 16;   // 75392
constexpr unsigned kLiveMaxOff = 133u * 512u;
constexpr unsigned kMergeOff   = 134u * 512u;
constexpr unsigned kDiagOff    = 135u * 512u;
}

__device__ float4       g_pos[2][kNAtoms];
__device__ unsigned int g_hist[2][256];
__device__ unsigned int g_done;

// ---------------------------------------------------------------------------
__global__ void prepack_kernel(const float* __restrict__ pred,
                               const float* __restrict__ tru,
                               const float* __restrict__ mask) {
    int i = blockIdx.x * blockDim.x + threadIdx.x;
    if (i == 0) g_done = 0u;
    if (i < 512) ((unsigned int*)g_hist)[i] = 0u;
    if (i >= kNAtoms) return;
    float m = mask[i];
    if (m != 0.0f) {
        g_pos[0][i] = make_float4(pred[3*i+0]*kPre, pred[3*i+1]*kPre, pred[3*i+2]*kPre, 0.f);
        g_pos[1][i] = make_float4(tru [3*i+0]*kPre, tru [3*i+1]*kPre, tru [3*i+2]*kPre, 0.f);
    } else {
        float dx = 1.0e8f + (float)i * 2.0e5f;   // displaced -> clamp word 203 -> dropped
        g_pos[0][i] = make_float4(dx, 0.f, 0.f, 0.f);
        g_pos[1][i] = make_float4(dx, 0.f, 0.f, 0.f);
    }
}

// ---------------------------------------------------------------------------
__device__ __forceinline__ void decode_tile(int p, int& bi, int& bj) {
    double Td = (double)kNTiles;
    int b = (int)(((2.0 * Td + 1.0) -
                   sqrt((2.0 * Td + 1.0) * (2.0 * Td + 1.0) - 8.0 * (double)p)) * 0.5);
    if (b < 0) b = 0;
    if (b > kNTiles - 1) b = kNTiles - 1;
    while (b * (2 * kNTiles - b + 1) / 2 > p) --b;
    while ((b + 1) * (2 * kNTiles - b) / 2 <= p) ++b;
    bi = b;
    bj = b + (p - b * (2 * kNTiles - b + 1) / 2);
}

// Rare (word 134..203): parity-packed u64 smem atomic. Adds (256-q) to bin w,
// q to bin w+1. Flush reads bins via pA[b] + pB[b+1] (b <= 201).
__device__ __forceinline__ void rare_add(unsigned* pA, unsigned* pB,
                                         unsigned w, unsigned q) {
    unsigned long long v = ((unsigned long long)q << 32)
                         | (unsigned long long)(256u - q);
    unsigned* addr = (w & 1u) ? (pB + w + 1) : (pA + w);
    atomicAdd((unsigned long long*)addr, v);
}

// Two pairs: scalar chain, 1 RMW/pair, rare routing, kill-safe.
__device__ __forceinline__ void process2(char* hb, unsigned* pA, unsigned* pB,
                                         float ax, float ay, float az,
                                         const float3 j0, const float3 j1,
                                         bool k0, bool k1) {
    float dx0 = ax - j0.x, dy0 = ay - j0.y, dz0 = az - j0.z;
    float dx1 = ax - j1.x, dy1 = ay - j1.y, dz1 = az - j1.z;
    float d20 = fmaf(dx0, dx0, fmaf(dy0, dy0, dz0 * dz0));
    float d21 = fmaf(dx1, dx1, fmaf(dy1, dy1, dz1 * dz1));
    float t0 = fminf(d20 * rsqrtf(d20), kClampT);    // d*256/STEP; NaN -> clamp
    float t1 = fminf(d21 * rsqrtf(d21), kClampT);
    unsigned b0 = __float_as_uint(t0 + 12582912.0f); // rn(t) in low mantissa
    unsigned b1 = __float_as_uint(t1 + 12582912.0f);
    unsigned q0 = b0 & 255u, q1 = b1 & 255u;
    unsigned off0 = (b0 & 0xFF00u) << 1;             // word * 512
    unsigned off1 = (b1 & 0xFF00u) << 1;
    bool rare0 = off0 > kLiveMaxOff;
    bool rare1 = off1 > kLiveMaxOff;
    if (k0) { off0 = kDiagOff; rare0 = false; }      // kill -> dead private word
    if (k1) { off1 = kDiagOff; rare1 = false; }
    unsigned val0 = q0 * 65535u + 256u;              // (256-q) | (q<<16)
    unsigned val1 = q1 * 65535u + 256u;
    if (!(rare0 || rare1)) {                         // hot path (~99.99%)
        if (off0 == off1) { val0 += val1; off1 = kMergeOff; }  // no lost update
        unsigned a0 = *(unsigned*)(hb + off0);
        unsigned a1 = *(unsigned*)(hb + off1);
        *(unsigned*)(hb + off0) = a0 + val0;
        *(unsigned*)(hb + off1) = a1 + val1;
    } else {
        if (rare0) rare_add(pA, pB, off0 >> 9, q0);
        else       *(unsigned*)(hb + off0) += val0;
        if (rare1) rare_add(pA, pB, off1 >> 9, q1);
        else       *(unsigned*)(hb + off1) += val1;
    }
}

// ---------------------------------------------------------------------------
__global__ __launch_bounds__(kThreads, 3)
void pair_hist_kernel(float* __restrict__ out) {
    extern __shared__ unsigned int smem[];
    unsigned int* hist = smem;                         // [136][128]
    unsigned int* pA   = smem + kHistU32;              // [208]
    unsigned int* pB   = pA + 208;                     // [208]
    float4* buf = (float4*)(pB + 208);                 // [256]

    const int s   = blockIdx.y;
    const int tid = threadIdx.x;
    const int tx  = tid & 15;     // cols tx*8 + v
    const int ty  = tid >> 4;     // rows ty*16 + u
    char* hb = (char*)hist + tid * 4;                  // bank = tid&31

#pragma unroll 4
    for (int w = 0; w < kWords; ++w) hist[(w << 7) + tid] = 0u;
    for (int k = tid; k < 2 * 208; k += kThreads) pA[k] = 0u;

    int p = blockIdx.x;
    int bi, bj;
    decode_tile(p, bi, bj);
    buf[tid]       = g_pos[s][bi * kTile + tid];
    buf[128 + tid] = g_pos[s][bj * kTile + tid];
    __syncthreads();

    for (;;) {
        const int pn = p + kBlocksX;
        const bool havenext = (pn < kNPairTiles);
        float4 na, nb; int bin_ = 0, bjn = 0;
        if (havenext) {                                // prefetch to registers
            decode_tile(pn, bin_, bjn);
            na = g_pos[s][bin_ * kTile + tid];
            nb = g_pos[s][bjn * kTile + tid];
        }

        const float4* ti = buf;
        const float4* tj = buf + 128;
        float3 rj[8];
#pragma unroll
        for (int v = 0; v < 8; ++v) {
            float4 t4 = tj[tx * 8 + v];
            rj[v] = make_float3(t4.x, t4.y, t4.z);
        }

        if (bi != bj) {
            for (int u0 = 0; u0 < 16; u0 += 4) {
#pragma unroll
                for (int uu = 0; uu < 4; ++uu) {
                    float4 a4 = ti[ty * 16 + u0 + uu];
#pragma unroll
                    for (int v = 0; v < 8; v += 2)
                        process2(hb, pA, pB, a4.x, a4.y, a4.z,
                                 rj[v], rj[v + 1], false, false);
                }
            }
        } else {
            for (int u0 = 0; u0 < 16; u0 += 4) {
#pragma unroll
                for (int uu = 0; uu < 4; ++uu) {
                    const int iu = ty * 16 + u0 + uu;
                    float4 a4 = ti[iu];
#pragma unroll
                    for (int v = 0; v < 8; v += 2) {
                        const int jv = tx * 8 + v;
                        process2(hb, pA, pB, a4.x, a4.y, a4.z,
                                 rj[v], rj[v + 1], iu >= jv, iu >= jv + 1);
                    }
                }
            }
        }

        __syncthreads();
        if (!havenext) break;
        buf[tid]       = na;
        buf[128 + tid] = nb;
        __syncthreads();
        p = pn; bi = bin_; bj = bjn;
    }

    // ---- flush ----
    // Private dual-field: word w low -> bin w, high -> bin w+1 (w 0..133).
    // Words 134 (merge) and 135 (diag) are dead: never read below.
    unsigned* slo = (unsigned*)buf;          // [136]
    unsigned* shi = slo + 136;               // [136]
#pragma unroll
    for (int c = 0; c < 2; ++c) {
        int w = tid + c * kThreads;
        if (w < kWords) {
            unsigned lo = 0, hi = 0;
            for (int i = 0; i < kThreads; ++i) {
                int t = (tid + i) & 127;                // staggered, conflict-free
                unsigned v = hist[(w << 7) + t];
                lo += v & 0xFFFFu;
                hi += v >> 16;
            }
            slo[w] = lo; shi[w] = hi;
        }
    }
    __syncthreads();
#pragma unroll
    for (int c = 0; c < 2; ++c) {
        int b = tid + c * kThreads;
        if (b <= 201) {
            unsigned tot = pA[b] + pB[b + 1];           // rare parity bins
            if (b <= 133) tot += slo[b];
            if (b >= 1 && b <= 134) tot += shi[b - 1];
            int dst = (b == 201) ? 200 : b;             // fold 201 -> 200
            if (tot) atomicAdd(&g_hist[s][dst], tot);
        }
    }

    // ---- last block finalizes ----
    __threadfence();
    __shared__ unsigned int ticket;
    __syncthreads();
    if (tid == 0) ticket = atomicAdd(&g_done, 1u);
    __syncthreads();
    if (ticket != 2u * kBlocksX - 1u) return;
    __threadfence();

    double* sh = (double*)smem;
    volatile unsigned int* gh = (volatile unsigned int*)g_hist;
    double h0a = (tid < kNBins) ? (double)gh[tid] : 0.0;
    double h0b = (tid + 128 < kNBins) ? (double)gh[tid + 128] : 0.0;
    double h1a = (tid < kNBins) ? (double)gh[256 + tid] : 0.0;
    double h1b = (tid + 128 < kNBins) ? (double)gh[256 + tid + 128] : 0.0;

    sh[tid] = h0a + h0b; __syncthreads();
    for (int o = 64; o > 0; o >>= 1) { if (tid < o) sh[tid] += sh[tid + o]; __syncthreads(); }
    double s0 = sh[0]; __syncthreads();

    sh[tid] = h1a + h1b; __syncthreads();
    for (int o = 64; o > 0; o >>= 1) { if (tid < o) sh[tid] += sh[tid + o]; __syncthreads(); }
    double s1 = sh[0]; __syncthreads();

    double inv0 = 1.0 / (s0 + 1e-12), inv1 = 1.0 / (s1 + 1e-12);
    sh[tid] = fabs(h0a * inv0 - h1a * inv1) + fabs(h0b * inv0 - h1b * inv1);
    __syncthreads();
    for (int o = 64; o > 0; o >>= 1) { if (tid < o) sh[tid] += sh[tid + o]; __syncthreads(); }

    if (tid == 0) out[0] = (float)sh[0];
}

// ---------------------------------------------------------------------------
extern "C" void kernel_launch(void* const* d_in, const int* in_sizes, int n_in,
                              void* d_out, int out_size) {
    (void)in_sizes; (void)n_in; (void)out_size;
    const float* pred = (const float*)d_in[0];
    const float* tru  = (const float*)d_in[1];
    const float* mask = (const float*)d_in[2];

    cudaFuncSetAttribute(pair_hist_kernel,
                         cudaFuncAttributeMaxDynamicSharedMemorySize, kSmemBytes);

    prepack_kernel<<<(kNAtoms + 255) / 256, 256>>>(pred, tru, mask);

    dim3 grid(kBlocksX, 2);
    pair_hist_kernel<<<grid, kThreads, kSmemBytes>>>((float*)d_out);
}